// round 5
// baseline (speedup 1.0000x reference)
#include <cuda_runtime.h>
#include <cuda_fp16.h>
#include <math.h>
#include <stdint.h>

// Problem constants
#define Bsz   4
#define Tn    4096
#define Dn    1024
#define Hn    8
#define MHn   2048
#define Mtok  (Bsz * Tn)          // 16384 tokens
#define EPSv  1e-6f

// GEMM tile config: 128x128 CTA tile, BK=64 per stage, 3 stages, 1 sync/iter
#define BM 128
#define BN 128
#define BKh 64                     // K-halves per stage
#define NST 3                      // pipeline stages
#define ASTRIDE 72                 // smem row stride in halves (144B) -> conflict-free ldmatrix
#define STAGE_A  (BM * ASTRIDE * 2)             // 18432 B
#define STAGE_B  (BN * ASTRIDE * 2)             // 18432 B
#define STAGEB   (STAGE_A + STAGE_B)            // 36864 B
#define SMEM_MMA (NST * STAGEB)                 // 110592 B

// ---------------------------------------------------------------------------
// Device-global scratch (no cudaMalloc).  Weights: exact-integer fp16 [N,K].
// ---------------------------------------------------------------------------
__device__ __half g_wq_in[(size_t)MHn * Dn];
__device__ __half g_wq_o [(size_t)Dn  * Dn];
__device__ __half g_wq_mi[(size_t)MHn * Dn];
__device__ __half g_wq_mo[(size_t)Dn  * MHn];
__device__ float g_sc_in[MHn];
__device__ float g_sc_o [Dn];
__device__ float g_sc_mi[MHn];
__device__ float g_sc_mo[Dn];
__device__ __half g_h    [(size_t)Mtok * Dn];    // rmsnorm out (reused for h2)
__device__ float  g_qkv  [(size_t)Mtok * MHn];   // qkv fp32
__device__ __half g_gated[(size_t)Mtok * Dn];    // gated fp16
__device__ __half g_act  [(size_t)Mtok * MHn];   // gelu out fp16
__device__ float  g_x2   [(size_t)Mtok * Dn];    // post-attn residual

// ---------------------------------------------------------------------------
// PTX helpers
// ---------------------------------------------------------------------------
__device__ __forceinline__ uint32_t smem_u32(const void* p) {
    return (uint32_t)__cvta_generic_to_shared(p);
}
__device__ __forceinline__ void cpa16(uint32_t s, const void* g) {
    asm volatile("cp.async.cg.shared.global [%0], [%1], 16;" :: "r"(s), "l"(g));
}
__device__ __forceinline__ void cpa_commit() {
    asm volatile("cp.async.commit_group;");
}
__device__ __forceinline__ void ldsm4(uint32_t& r0, uint32_t& r1, uint32_t& r2, uint32_t& r3,
                                      uint32_t addr) {
    asm volatile("ldmatrix.sync.aligned.m8n8.x4.shared.b16 {%0,%1,%2,%3}, [%4];"
                 : "=r"(r0), "=r"(r1), "=r"(r2), "=r"(r3) : "r"(addr));
}
__device__ __forceinline__ void mma16816(float* c, uint32_t a0, uint32_t a1, uint32_t a2,
                                         uint32_t a3, uint32_t b0, uint32_t b1) {
    asm volatile("mma.sync.aligned.m16n8k16.row.col.f32.f16.f16.f32 "
                 "{%0,%1,%2,%3}, {%4,%5,%6,%7}, {%8,%9}, {%0,%1,%2,%3};"
                 : "+f"(c[0]), "+f"(c[1]), "+f"(c[2]), "+f"(c[3])
                 : "r"(a0), "r"(a1), "r"(a2), "r"(a3), "r"(b0), "r"(b1));
}

// ---------------------------------------------------------------------------
// Quantize: wq[n,k] = fp16(round(w/scale))  (exact integers), scales[n]=scale
// ---------------------------------------------------------------------------
__global__ void quantize_rows_kernel(const float* __restrict__ w,
                                     __half* __restrict__ wq,
                                     float* __restrict__ scales, int C) {
    int row = blockIdx.x;
    const float* wr = w + (size_t)row * C;
    float m = 0.f;
    for (int i = threadIdx.x; i < C; i += blockDim.x)
        m = fmaxf(m, fabsf(wr[i]));
    __shared__ float sh[32];
    int lane = threadIdx.x & 31, wid = threadIdx.x >> 5;
#pragma unroll
    for (int o = 16; o; o >>= 1) m = fmaxf(m, __shfl_xor_sync(0xffffffffu, m, o));
    if (lane == 0) sh[wid] = m;
    __syncthreads();
    if (wid == 0) {
        float v = (lane < (blockDim.x >> 5)) ? sh[lane] : 0.f;
#pragma unroll
        for (int o = 16; o; o >>= 1) v = fmaxf(v, __shfl_xor_sync(0xffffffffu, v, o));
        if (lane == 0) sh[0] = v;
    }
    __syncthreads();
    float scale = fmaxf(sh[0] * (1.0f / 127.0f), 1e-8f);
    if (threadIdx.x == 0) scales[row] = scale;
    for (int i = threadIdx.x; i < C; i += blockDim.x)
        wq[(size_t)row * C + i] = __float2half_rn(rintf(wr[i] / scale));
}

// ---------------------------------------------------------------------------
// RMSNorm -> fp16
// ---------------------------------------------------------------------------
__global__ void rmsnorm_kernel(const float* __restrict__ x,
                               const float* __restrict__ w,
                               __half* __restrict__ out) {
    int row = blockIdx.x;
    const float* xr = x + (size_t)row * Dn;
    float ss = 0.f;
    for (int i = threadIdx.x; i < Dn; i += blockDim.x) {
        float v = xr[i];
        ss += v * v;
    }
    __shared__ float sh[32];
    int lane = threadIdx.x & 31, wid = threadIdx.x >> 5;
#pragma unroll
    for (int o = 16; o; o >>= 1) ss += __shfl_xor_sync(0xffffffffu, ss, o);
    if (lane == 0) sh[wid] = ss;
    __syncthreads();
    if (wid == 0) {
        float v = (lane < (blockDim.x >> 5)) ? sh[lane] : 0.f;
#pragma unroll
        for (int o = 16; o; o >>= 1) v += __shfl_xor_sync(0xffffffffu, v, o);
        if (lane == 0) sh[0] = v;
    }
    __syncthreads();
    float inv = rsqrtf(sh[0] * (1.0f / Dn) + EPSv);
    for (int i = threadIdx.x; i < Dn; i += blockDim.x)
        out[(size_t)row * Dn + i] = __float2half_rn(xr[i] * inv * w[i]);
}

// ---------------------------------------------------------------------------
// Causal exp-filter conv (linear recurrence, chunked w/ 512-step warmup) + SiLU
// ---------------------------------------------------------------------------
#define SCH 512
__global__ void scan_gate_kernel(const float* __restrict__ qkv,
                                 const float* __restrict__ filt,
                                 __half* __restrict__ gated) {
    int tid = threadIdx.x;
    int chunk = blockIdx.x & 7;
    int b = (blockIdx.x >> 3) & 3;
    int cg = blockIdx.x >> 5;
    int c = cg * 256 + tid;
    int h = c >> 7;
    float f0 = filt[h];
    float alpha = filt[Hn + h] / f0;
    const float* base = qkv + (size_t)b * Tn * MHn;
    __half* ob = gated + (size_t)b * Tn * Dn;
    float y = 0.f;
    int t0 = chunk * SCH;
    if (chunk) {
#pragma unroll 4
        for (int t = t0 - SCH; t < t0; ++t)
            y = fmaf(alpha, y, base[(size_t)t * MHn + c]);
    }
#pragma unroll 2
    for (int t = t0; t < t0 + SCH; ++t) {
        float s = base[(size_t)t * MHn + c];
        float g = base[(size_t)t * MHn + Dn + c];
        y = fmaf(alpha, y, s);
        float sig = 1.0f / (1.0f + expf(-g));
        ob[(size_t)t * Dn + c] = __float2half_rn((f0 * y) * (g * sig));
    }
}

// ---------------------------------------------------------------------------
// fp16 tensor-core GEMM: v[m,n] = (sum_k A[m,k]*W[n,k]) * scales[n]
//   EPI 0: Cf = v     EPI 1: Cf = v + Add     EPI 2: Ch = fp16(gelu(v))
// 128x128 tile, BK=64 stage, 3-stage ring, prefetch distance 2,
// ONE __syncthreads per K-iteration. 256 threads, 2 CTAs/SM.
// ---------------------------------------------------------------------------
template <int EPI>
__global__ __launch_bounds__(256, 2)
void mma_gemm(const __half* __restrict__ A, const __half* __restrict__ W,
              const float* __restrict__ scales, const float* __restrict__ Add,
              float* __restrict__ Cf, __half* __restrict__ Ch,
              int M, int N, int K) {
    extern __shared__ char smem[];
    uint32_t s0 = smem_u32(smem);

    int tid = threadIdx.x;
    int bm = blockIdx.y * BM;
    int bn = blockIdx.x * BN;
    int lane = tid & 31, wid = tid >> 5;
    int wm = wid >> 1, wn = wid & 1;

    // loader mapping: 2 threads per 128-row, 4 16B-chunks each
    int lr = tid >> 1;          // 0..127 row
    int lh = tid & 1;           // which half of the 8 chunks

    const __half* Ab = A + (size_t)(bm + lr) * K + lh * 32;
    const __half* Bb = W + (size_t)(bn + lr) * K + lh * 32;
    uint32_t soff = (uint32_t)(lr * ASTRIDE + lh * 32) * 2;

    auto load_tile = [&](int kt) {
        int st = kt % NST;
        uint32_t tb = s0 + st * STAGEB;
        const __half* ag = Ab + (size_t)kt * BKh;
        const __half* bg = Bb + (size_t)kt * BKh;
#pragma unroll
        for (int c = 0; c < 4; ++c) {
            cpa16(tb + soff + c * 16, ag + c * 8);
            cpa16(tb + STAGE_A + soff + c * 16, bg + c * 8);
        }
        cpa_commit();
    };

    float c[2][8][4];
#pragma unroll
    for (int i = 0; i < 2; ++i)
#pragma unroll
        for (int j = 0; j < 8; ++j)
#pragma unroll
            for (int l = 0; l < 4; ++l) c[i][j][l] = 0.f;

    int KT = K / BKh;
    load_tile(0);
    load_tile(1);

    for (int kt = 0; kt < KT; ++kt) {
        if (kt + 1 < KT) asm volatile("cp.async.wait_group 1;");
        else             asm volatile("cp.async.wait_group 0;");
        __syncthreads();                    // all warps done with iter kt-1; tile kt visible

        if (kt + 2 < KT) load_tile(kt + 2); // overwrites buffer of kt-1: safe after sync

        uint32_t aBase = s0 + (kt % NST) * STAGEB;
        uint32_t bBase = aBase + STAGE_A;
#pragma unroll
        for (int ks = 0; ks < 4; ++ks) {
            uint32_t a[2][4];
#pragma unroll
            for (int mt = 0; mt < 2; ++mt) {
                int row = wm * 32 + mt * 16 + (lane & 15);
                int col = ks * 16 + (lane >> 4) * 8;
                ldsm4(a[mt][0], a[mt][1], a[mt][2], a[mt][3],
                      aBase + (row * ASTRIDE + col) * 2);
            }
            uint32_t b[4][4];
#pragma unroll
            for (int p = 0; p < 4; ++p) {
                int nrow = wn * 64 + p * 16 + (lane & 7) + ((lane >> 4) << 3);
                int col = ks * 16 + ((lane >> 3) & 1) * 8;
                ldsm4(b[p][0], b[p][1], b[p][2], b[p][3],
                      bBase + (nrow * ASTRIDE + col) * 2);
            }
#pragma unroll
            for (int mt = 0; mt < 2; ++mt)
#pragma unroll
                for (int nt = 0; nt < 8; ++nt)
                    mma16816(c[mt][nt], a[mt][0], a[mt][1], a[mt][2], a[mt][3],
                             b[nt >> 1][(nt & 1) * 2], b[nt >> 1][(nt & 1) * 2 + 1]);
        }
    }

    // Epilogue
#pragma unroll
    for (int mt = 0; mt < 2; ++mt) {
#pragma unroll
        for (int nt = 0; nt < 8; ++nt) {
            int r0 = bm + wm * 32 + mt * 16 + (lane >> 2);
            int col = bn + wn * 64 + nt * 8 + (lane & 3) * 2;
            float sc0 = __ldg(&scales[col]);
            float sc1 = __ldg(&scales[col + 1]);
#pragma unroll
            for (int half = 0; half < 2; ++half) {
                int row = r0 + half * 8;
                float v0 = c[mt][nt][half * 2 + 0] * sc0;
                float v1 = c[mt][nt][half * 2 + 1] * sc1;
                if (EPI == 0) {
                    float2 o = {v0, v1};
                    *(float2*)&Cf[(size_t)row * N + col] = o;
                } else if (EPI == 1) {
                    float2 r = *(const float2*)&Add[(size_t)row * N + col];
                    float2 o = {v0 + r.x, v1 + r.y};
                    *(float2*)&Cf[(size_t)row * N + col] = o;
                } else {
                    float g0 = 0.5f * v0 * (1.0f + erff(v0 * 0.70710678118654752440f));
                    float g1 = 0.5f * v1 * (1.0f + erff(v1 * 0.70710678118654752440f));
                    __half2 o = {__float2half_rn(g0), __float2half_rn(g1)};
                    *(__half2*)&Ch[(size_t)row * N + col] = o;
                }
            }
        }
    }
}

// ---------------------------------------------------------------------------
// Launch
// ---------------------------------------------------------------------------
extern "C" void kernel_launch(void* const* d_in, const int* in_sizes, int n_in,
                              void* d_out, int out_size) {
    (void)in_sizes; (void)n_in; (void)out_size;
    const float* x    = (const float*)d_in[0];
    const float* n1w  = (const float*)d_in[1];
    const float* n2w  = (const float*)d_in[2];
    const float* w_in = (const float*)d_in[3];
    const float* w_o  = (const float*)d_in[4];
    const float* w_mi = (const float*)d_in[5];
    const float* w_mo = (const float*)d_in[6];
    const float* filt = (const float*)d_in[7];
    float* out = (float*)d_out;

    __half *p_wq_in, *p_wq_o, *p_wq_mi, *p_wq_mo, *p_h, *p_gated, *p_act;
    float *p_sc_in, *p_sc_o, *p_sc_mi, *p_sc_mo, *p_qkv, *p_x2;
    cudaGetSymbolAddress((void**)&p_wq_in, g_wq_in);
    cudaGetSymbolAddress((void**)&p_wq_o,  g_wq_o);
    cudaGetSymbolAddress((void**)&p_wq_mi, g_wq_mi);
    cudaGetSymbolAddress((void**)&p_wq_mo, g_wq_mo);
    cudaGetSymbolAddress((void**)&p_sc_in, g_sc_in);
    cudaGetSymbolAddress((void**)&p_sc_o,  g_sc_o);
    cudaGetSymbolAddress((void**)&p_sc_mi, g_sc_mi);
    cudaGetSymbolAddress((void**)&p_sc_mo, g_sc_mo);
    cudaGetSymbolAddress((void**)&p_h,     g_h);
    cudaGetSymbolAddress((void**)&p_qkv,   g_qkv);
    cudaGetSymbolAddress((void**)&p_gated, g_gated);
    cudaGetSymbolAddress((void**)&p_act,   g_act);
    cudaGetSymbolAddress((void**)&p_x2,    g_x2);

    cudaFuncSetAttribute(mma_gemm<0>, cudaFuncAttributeMaxDynamicSharedMemorySize, SMEM_MMA);
    cudaFuncSetAttribute(mma_gemm<1>, cudaFuncAttributeMaxDynamicSharedMemorySize, SMEM_MMA);
    cudaFuncSetAttribute(mma_gemm<2>, cudaFuncAttributeMaxDynamicSharedMemorySize, SMEM_MMA);

    // 1) quantize weights -> exact fp16 integers + scales
    quantize_rows_kernel<<<MHn, 256>>>(w_in, p_wq_in, p_sc_in, Dn);
    quantize_rows_kernel<<<Dn,  256>>>(w_o,  p_wq_o,  p_sc_o,  Dn);
    quantize_rows_kernel<<<MHn, 256>>>(w_mi, p_wq_mi, p_sc_mi, Dn);
    quantize_rows_kernel<<<Dn,  256>>>(w_mo, p_wq_mo, p_sc_mo, MHn);

    // 2) h = rmsnorm(x) -> fp16
    rmsnorm_kernel<<<Mtok, 256>>>(x, n1w, p_h);

    // 3) qkv = h @ Wq_in^T (fp32 out)
    mma_gemm<0><<<dim3(MHn / BN, Mtok / BM), 256, SMEM_MMA>>>(
        p_h, p_wq_in, p_sc_in, nullptr, p_qkv, nullptr, Mtok, MHn, Dn);

    // 4) causal conv recurrence + SiLU gate -> fp16
    scan_gate_kernel<<<128, 256>>>(p_qkv, filt, p_gated);

    // 5) x2 = x + gated @ Wq_o^T
    mma_gemm<1><<<dim3(Dn / BN, Mtok / BM), 256, SMEM_MMA>>>(
        p_gated, p_wq_o, p_sc_o, x, p_x2, nullptr, Mtok, Dn, Dn);

    // 6) h2 = rmsnorm(x2) -> fp16
    rmsnorm_kernel<<<Mtok, 256>>>(p_x2, n2w, p_h);

    // 7) m = gelu(h2 @ Wq_mi^T) -> fp16
    mma_gemm<2><<<dim3(MHn / BN, Mtok / BM), 256, SMEM_MMA>>>(
        p_h, p_wq_mi, p_sc_mi, nullptr, nullptr, p_act, Mtok, MHn, Dn);

    // 8) out = x2 + m @ Wq_mo^T
    mma_gemm<1><<<dim3(Dn / BN, Mtok / BM), 256, SMEM_MMA>>>(
        p_act, p_wq_mo, p_sc_mo, p_x2, out, nullptr, Mtok, Dn, MHn);
}

// round 7
// speedup vs baseline: 1.5131x; 1.5131x over previous
#include <cuda_runtime.h>
#include <cuda_fp16.h>
#include <math.h>
#include <stdint.h>

// Problem constants
#define Bsz   4
#define Tn    4096
#define Dn    1024
#define Hn    8
#define MHn   2048
#define Mtok  (Bsz * Tn)          // 16384 tokens
#define EPSv  1e-6f

// GEMM tile config: 128(M) x 256(N) CTA tile, BK=32 per stage, 4 stages,
// prefetch distance 3, one __syncthreads per K-iteration, 512 threads.
#define BM 128
#define BN 256
#define BKh 32                     // K-halves per stage
#define NST 4                      // pipeline stages
#define ASTRIDE 40                 // smem row stride in halves -> conflict-free ldmatrix
#define STAGE_A  (BM * ASTRIDE * 2)             // 10240 B
#define STAGE_B  (BN * ASTRIDE * 2)             // 20480 B
#define STAGEB   (STAGE_A + STAGE_B)            // 30720 B
#define SMEM_MMA (NST * STAGEB)                 // 122880 B

// ---------------------------------------------------------------------------
// Device-global scratch (no cudaMalloc).  Weights: exact-integer fp16 [N,K].
// ---------------------------------------------------------------------------
__device__ __half g_wq_in[(size_t)MHn * Dn];
__device__ __half g_wq_o [(size_t)Dn  * Dn];
__device__ __half g_wq_mi[(size_t)MHn * Dn];
__device__ __half g_wq_mo[(size_t)Dn  * MHn];
__device__ float g_sc_in[MHn];
__device__ float g_sc_o [Dn];
__device__ float g_sc_mi[MHn];
__device__ float g_sc_mo[Dn];
__device__ __half g_h    [(size_t)Mtok * Dn];    // rmsnorm out (reused for h2)
__device__ float  g_qkv  [(size_t)Mtok * MHn];   // qkv fp32
__device__ __half g_gated[(size_t)Mtok * Dn];    // gated fp16
__device__ __half g_act  [(size_t)Mtok * MHn];   // gelu out fp16
__device__ float  g_x2   [(size_t)Mtok * Dn];    // post-attn residual

// ---------------------------------------------------------------------------
// PTX helpers
// ---------------------------------------------------------------------------
__device__ __forceinline__ uint32_t smem_u32(const void* p) {
    return (uint32_t)__cvta_generic_to_shared(p);
}
__device__ __forceinline__ void cpa16(uint32_t s, const void* g) {
    asm volatile("cp.async.cg.shared.global [%0], [%1], 16;" :: "r"(s), "l"(g));
}
__device__ __forceinline__ void cpa_commit() {
    asm volatile("cp.async.commit_group;");
}
__device__ __forceinline__ void ldsm4(uint32_t& r0, uint32_t& r1, uint32_t& r2, uint32_t& r3,
                                      uint32_t addr) {
    asm volatile("ldmatrix.sync.aligned.m8n8.x4.shared.b16 {%0,%1,%2,%3}, [%4];"
                 : "=r"(r0), "=r"(r1), "=r"(r2), "=r"(r3) : "r"(addr));
}
__device__ __forceinline__ void mma16816(float* c, uint32_t a0, uint32_t a1, uint32_t a2,
                                         uint32_t a3, uint32_t b0, uint32_t b1) {
    asm volatile("mma.sync.aligned.m16n8k16.row.col.f32.f16.f16.f32 "
                 "{%0,%1,%2,%3}, {%4,%5,%6,%7}, {%8,%9}, {%0,%1,%2,%3};"
                 : "+f"(c[0]), "+f"(c[1]), "+f"(c[2]), "+f"(c[3])
                 : "r"(a0), "r"(a1), "r"(a2), "r"(a3), "r"(b0), "r"(b1));
}

// ---------------------------------------------------------------------------
// Quantize: wq[n,k] = fp16(round(w/scale))  (exact integers), scales[n]=scale
// ---------------------------------------------------------------------------
__global__ void quantize_rows_kernel(const float* __restrict__ w,
                                     __half* __restrict__ wq,
                                     float* __restrict__ scales, int C) {
    int row = blockIdx.x;
    const float* wr = w + (size_t)row * C;
    float m = 0.f;
    for (int i = threadIdx.x; i < C; i += blockDim.x)
        m = fmaxf(m, fabsf(wr[i]));
    __shared__ float sh[32];
    int lane = threadIdx.x & 31, wid = threadIdx.x >> 5;
#pragma unroll
    for (int o = 16; o; o >>= 1) m = fmaxf(m, __shfl_xor_sync(0xffffffffu, m, o));
    if (lane == 0) sh[wid] = m;
    __syncthreads();
    if (wid == 0) {
        float v = (lane < (blockDim.x >> 5)) ? sh[lane] : 0.f;
#pragma unroll
        for (int o = 16; o; o >>= 1) v = fmaxf(v, __shfl_xor_sync(0xffffffffu, v, o));
        if (lane == 0) sh[0] = v;
    }
    __syncthreads();
    float scale = fmaxf(sh[0] * (1.0f / 127.0f), 1e-8f);
    if (threadIdx.x == 0) scales[row] = scale;
    for (int i = threadIdx.x; i < C; i += blockDim.x)
        wq[(size_t)row * C + i] = __float2half_rn(rintf(wr[i] / scale));
}

// ---------------------------------------------------------------------------
// RMSNorm -> fp16
// ---------------------------------------------------------------------------
__global__ void rmsnorm_kernel(const float* __restrict__ x,
                               const float* __restrict__ w,
                               __half* __restrict__ out) {
    int row = blockIdx.x;
    const float* xr = x + (size_t)row * Dn;
    float ss = 0.f;
    for (int i = threadIdx.x; i < Dn; i += blockDim.x) {
        float v = xr[i];
        ss += v * v;
    }
    __shared__ float sh[32];
    int lane = threadIdx.x & 31, wid = threadIdx.x >> 5;
#pragma unroll
    for (int o = 16; o; o >>= 1) ss += __shfl_xor_sync(0xffffffffu, ss, o);
    if (lane == 0) sh[wid] = ss;
    __syncthreads();
    if (wid == 0) {
        float v = (lane < (blockDim.x >> 5)) ? sh[lane] : 0.f;
#pragma unroll
        for (int o = 16; o; o >>= 1) v += __shfl_xor_sync(0xffffffffu, v, o);
        if (lane == 0) sh[0] = v;
    }
    __syncthreads();
    float inv = rsqrtf(sh[0] * (1.0f / Dn) + EPSv);
    for (int i = threadIdx.x; i < Dn; i += blockDim.x)
        out[(size_t)row * Dn + i] = __float2half_rn(xr[i] * inv * w[i]);
}

// ---------------------------------------------------------------------------
// Causal exp-filter conv (linear recurrence, chunked w/ 512-step warmup) + SiLU
// ---------------------------------------------------------------------------
#define SCH 512
__global__ void scan_gate_kernel(const float* __restrict__ qkv,
                                 const float* __restrict__ filt,
                                 __half* __restrict__ gated) {
    int tid = threadIdx.x;
    int chunk = blockIdx.x & 7;
    int b = (blockIdx.x >> 3) & 3;
    int cg = blockIdx.x >> 5;
    int c = cg * 256 + tid;
    int h = c >> 7;
    float f0 = filt[h];
    float alpha = filt[Hn + h] / f0;
    const float* base = qkv + (size_t)b * Tn * MHn;
    __half* ob = gated + (size_t)b * Tn * Dn;
    float y = 0.f;
    int t0 = chunk * SCH;
    if (chunk) {
#pragma unroll 4
        for (int t = t0 - SCH; t < t0; ++t)
            y = fmaf(alpha, y, base[(size_t)t * MHn + c]);
    }
#pragma unroll 2
    for (int t = t0; t < t0 + SCH; ++t) {
        float s = base[(size_t)t * MHn + c];
        float g = base[(size_t)t * MHn + Dn + c];
        y = fmaf(alpha, y, s);
        float sig = 1.0f / (1.0f + expf(-g));
        ob[(size_t)t * Dn + c] = __float2half_rn((f0 * y) * (g * sig));
    }
}

// ---------------------------------------------------------------------------
// fp16 tensor-core GEMM: v[m,n] = (sum_k A[m,k]*W[n,k]) * scales[n]
//   EPI 0: Cf = v     EPI 1: Cf = v + Add     EPI 2: Ch = fp16(gelu(v))
// 128x256 tile, BK=32, 512 thr (16 warps: 4m x 4n), NST=4, prefetch 3,
// wait_group 2 steady-state, ONE __syncthreads per iteration.
// ---------------------------------------------------------------------------
template <int EPI>
__global__ __launch_bounds__(512)
void mma_gemm(const __half* __restrict__ A, const __half* __restrict__ W,
              const float* __restrict__ scales, const float* __restrict__ Add,
              float* __restrict__ Cf, __half* __restrict__ Ch,
              int M, int N, int K) {
    extern __shared__ char smem[];
    uint32_t s0 = smem_u32(smem);

    int tid = threadIdx.x;
    int bm = blockIdx.y * BM;
    int bn = blockIdx.x * BN;
    int lane = tid & 31, wid = tid >> 5;
    int wm = wid & 3;            // 4 m-groups of 32 rows
    int wn = wid >> 2;           // 4 n-groups of 64 cols

    // loader: A 128 rows x 64B -> 512 chunks (1/thread); B 256 rows x 64B -> 2/thread
    int lr = tid >> 2;           // 0..127
    int lc = tid & 3;            // 16B chunk in row

    const __half* Ab = A + (size_t)(bm + lr) * K + lc * 8;
    const __half* B0 = W + (size_t)(bn + lr) * K + lc * 8;
    const __half* B1 = W + (size_t)(bn + 128 + lr) * K + lc * 8;
    uint32_t aoff = (uint32_t)(lr * ASTRIDE + lc * 8) * 2;
    uint32_t boff1 = (uint32_t)((128 + lr) * ASTRIDE + lc * 8) * 2;
    uint32_t boff0 = (uint32_t)(lr * ASTRIDE + lc * 8) * 2;

    auto load_tile = [&](int kt) {
        uint32_t tb = s0 + (kt & (NST - 1)) * STAGEB;
        const __half* ag = Ab + (size_t)kt * BKh;
        cpa16(tb + aoff, ag);
        cpa16(tb + STAGE_A + boff0, B0 + (size_t)kt * BKh);
        cpa16(tb + STAGE_A + boff1, B1 + (size_t)kt * BKh);
        cpa_commit();
    };

    float c[2][8][4];
#pragma unroll
    for (int i = 0; i < 2; ++i)
#pragma unroll
        for (int j = 0; j < 8; ++j)
#pragma unroll
            for (int l = 0; l < 4; ++l) c[i][j][l] = 0.f;

    int KT = K / BKh;
    load_tile(0);
    load_tile(1);
    load_tile(2);

    for (int kt = 0; kt < KT; ++kt) {
        if (kt < KT - 2)       asm volatile("cp.async.wait_group 2;");
        else if (kt == KT - 2) asm volatile("cp.async.wait_group 1;");
        else                   asm volatile("cp.async.wait_group 0;");
        __syncthreads();                    // warps done with kt-1; tile kt visible

        if (kt + 3 < KT) load_tile(kt + 3); // overwrites buffer of kt-1: safe

        uint32_t aBase = s0 + (kt & (NST - 1)) * STAGEB;
        uint32_t bBase = aBase + STAGE_A;
#pragma unroll
        for (int ks = 0; ks < 2; ++ks) {
            uint32_t a[2][4];
#pragma unroll
            for (int mt = 0; mt < 2; ++mt) {
                int row = wm * 32 + mt * 16 + (lane & 15);
                int col = ks * 16 + (lane >> 4) * 8;
                ldsm4(a[mt][0], a[mt][1], a[mt][2], a[mt][3],
                      aBase + (row * ASTRIDE + col) * 2);
            }
            uint32_t b[4][4];
#pragma unroll
            for (int p = 0; p < 4; ++p) {
                int nrow = wn * 64 + p * 16 + (lane & 7) + ((lane >> 4) << 3);
                int col = ks * 16 + ((lane >> 3) & 1) * 8;
                ldsm4(b[p][0], b[p][1], b[p][2], b[p][3],
                      bBase + (nrow * ASTRIDE + col) * 2);
            }
#pragma unroll
            for (int mt = 0; mt < 2; ++mt)
#pragma unroll
                for (int nt = 0; nt < 8; ++nt)
                    mma16816(c[mt][nt], a[mt][0], a[mt][1], a[mt][2], a[mt][3],
                             b[nt >> 1][(nt & 1) * 2], b[nt >> 1][(nt & 1) * 2 + 1]);
        }
    }

    // Epilogue
#pragma unroll
    for (int mt = 0; mt < 2; ++mt) {
#pragma unroll
        for (int nt = 0; nt < 8; ++nt) {
            int r0 = bm + wm * 32 + mt * 16 + (lane >> 2);
            int col = bn + wn * 64 + nt * 8 + (lane & 3) * 2;
            float sc0 = __ldg(&scales[col]);
            float sc1 = __ldg(&scales[col + 1]);
#pragma unroll
            for (int half = 0; half < 2; ++half) {
                int row = r0 + half * 8;
                float v0 = c[mt][nt][half * 2 + 0] * sc0;
                float v1 = c[mt][nt][half * 2 + 1] * sc1;
                if (EPI == 0) {
                    float2 o = {v0, v1};
                    *(float2*)&Cf[(size_t)row * N + col] = o;
                } else if (EPI == 1) {
                    float2 r = *(const float2*)&Add[(size_t)row * N + col];
                    float2 o = {v0 + r.x, v1 + r.y};
                    *(float2*)&Cf[(size_t)row * N + col] = o;
                } else {
                    float g0 = 0.5f * v0 * (1.0f + erff(v0 * 0.70710678118654752440f));
                    float g1 = 0.5f * v1 * (1.0f + erff(v1 * 0.70710678118654752440f));
                    __half2 o = {__float2half_rn(g0), __float2half_rn(g1)};
                    *(__half2*)&Ch[(size_t)row * N + col] = o;
                }
            }
        }
    }
}

// ---------------------------------------------------------------------------
// Launch
// ---------------------------------------------------------------------------
extern "C" void kernel_launch(void* const* d_in, const int* in_sizes, int n_in,
                              void* d_out, int out_size) {
    (void)in_sizes; (void)n_in; (void)out_size;
    const float* x    = (const float*)d_in[0];
    const float* n1w  = (const float*)d_in[1];
    const float* n2w  = (const float*)d_in[2];
    const float* w_in = (const float*)d_in[3];
    const float* w_o  = (const float*)d_in[4];
    const float* w_mi = (const float*)d_in[5];
    const float* w_mo = (const float*)d_in[6];
    const float* filt = (const float*)d_in[7];
    float* out = (float*)d_out;

    __half *p_wq_in, *p_wq_o, *p_wq_mi, *p_wq_mo, *p_h, *p_gated, *p_act;
    float *p_sc_in, *p_sc_o, *p_sc_mi, *p_sc_mo, *p_qkv, *p_x2;
    cudaGetSymbolAddress((void**)&p_wq_in, g_wq_in);
    cudaGetSymbolAddress((void**)&p_wq_o,  g_wq_o);
    cudaGetSymbolAddress((void**)&p_wq_mi, g_wq_mi);
    cudaGetSymbolAddress((void**)&p_wq_mo, g_wq_mo);
    cudaGetSymbolAddress((void**)&p_sc_in, g_sc_in);
    cudaGetSymbolAddress((void**)&p_sc_o,  g_sc_o);
    cudaGetSymbolAddress((void**)&p_sc_mi, g_sc_mi);
    cudaGetSymbolAddress((void**)&p_sc_mo, g_sc_mo);
    cudaGetSymbolAddress((void**)&p_h,     g_h);
    cudaGetSymbolAddress((void**)&p_qkv,   g_qkv);
    cudaGetSymbolAddress((void**)&p_gated, g_gated);
    cudaGetSymbolAddress((void**)&p_act,   g_act);
    cudaGetSymbolAddress((void**)&p_x2,    g_x2);

    cudaFuncSetAttribute(mma_gemm<0>, cudaFuncAttributeMaxDynamicSharedMemorySize, SMEM_MMA);
    cudaFuncSetAttribute(mma_gemm<1>, cudaFuncAttributeMaxDynamicSharedMemorySize, SMEM_MMA);
    cudaFuncSetAttribute(mma_gemm<2>, cudaFuncAttributeMaxDynamicSharedMemorySize, SMEM_MMA);

    // 1) quantize weights -> exact fp16 integers + scales
    quantize_rows_kernel<<<MHn, 256>>>(w_in, p_wq_in, p_sc_in, Dn);
    quantize_rows_kernel<<<Dn,  256>>>(w_o,  p_wq_o,  p_sc_o,  Dn);
    quantize_rows_kernel<<<MHn, 256>>>(w_mi, p_wq_mi, p_sc_mi, Dn);
    quantize_rows_kernel<<<Dn,  256>>>(w_mo, p_wq_mo, p_sc_mo, MHn);

    // 2) h = rmsnorm(x) -> fp16
    rmsnorm_kernel<<<Mtok, 256>>>(x, n1w, p_h);

    // 3) qkv = h @ Wq_in^T (fp32 out)
    mma_gemm<0><<<dim3(MHn / BN, Mtok / BM), 512, SMEM_MMA>>>(
        p_h, p_wq_in, p_sc_in, nullptr, p_qkv, nullptr, Mtok, MHn, Dn);

    // 4) causal conv recurrence + SiLU gate -> fp16
    scan_gate_kernel<<<128, 256>>>(p_qkv, filt, p_gated);

    // 5) x2 = x + gated @ Wq_o^T
    mma_gemm<1><<<dim3(Dn / BN, Mtok / BM), 512, SMEM_MMA>>>(
        p_gated, p_wq_o, p_sc_o, x, p_x2, nullptr, Mtok, Dn, Dn);

    // 6) h2 = rmsnorm(x2) -> fp16
    rmsnorm_kernel<<<Mtok, 256>>>(p_x2, n2w, p_h);

    // 7) m = gelu(h2 @ Wq_mi^T) -> fp16
    mma_gemm<2><<<dim3(MHn / BN, Mtok / BM), 512, SMEM_MMA>>>(
        p_h, p_wq_mi, p_sc_mi, nullptr, nullptr, p_act, Mtok, MHn, Dn);

    // 8) out = x2 + m @ Wq_mo^T
    mma_gemm<1><<<dim3(Dn / BN, Mtok / BM), 512, SMEM_MMA>>>(
        p_act, p_wq_mo, p_sc_mo, p_x2, out, nullptr, Mtok, Dn, MHn);
}